// round 14
// baseline (speedup 1.0000x reference)
#include <cuda_runtime.h>
#include <cuda_bf16.h>
#include <cstdint>

#define NN 193536
#define BB 16
#define CC 9
#define KK 1000
#define BC 144            // BB*CC
#define MAXDET 100
#define SCORE_T 0.05f
#define IOU_T 0.5f

// keys are positive floats in (0.05, 1): 20-bit prefixes span [0x3D4CC, 0x3F7FF]
#define P_LO 0x3D4CCu
#define HB 9012
#define HBPAD 9024        // padded to 282*32
#define KT_MIN 0x3D4CCCCEu   // smallest uint key with float > 0.05f

// ---------------- scratch (static device globals; no dynamic alloc) ----------------
__device__ float    g_scores[(size_t)BC * NN];       // ~111.5 MB, [(b*9+c)][n]
__device__ float    g_topval[BC * KK];
__device__ float4   g_topbox[BC * KK];
__device__ float    g_val[BC * KK];                  // post-NMS score (0 for invalid)
__device__ float    g_cval[BC * KK];                 // compacted survivors (desc order)
__device__ int      g_cidx[BC * KK];
__device__ int      g_cnt[BC];

// ---------------- K1: sigmoid + transpose scores to class-major ----------------
__global__ __launch_bounds__(256) void score_kernel(const float* __restrict__ cls,
                                                    const float* __restrict__ obj) {
    int b = blockIdx.y;
    int n0 = blockIdx.x * 256;
    int tid = threadIdx.x;
    __shared__ float sh[256 * 9];
    const float* src = cls + ((size_t)b * NN + n0) * 9;
    for (int i = tid; i < 2304; i += 256) sh[i] = src[i];
    __syncthreads();
    int n = n0 + tid;
    float so = 1.0f / (1.0f + expf(-obj[(size_t)b * NN + n]));
#pragma unroll
    for (int c = 0; c < 9; c++) {
        float s = 1.0f / (1.0f + expf(-sh[tid * 9 + c]));
        g_scores[((size_t)(b * 9 + c)) * NN + n] = s * so;
    }
}

// ---------------- scan helper: boundary bin from top, given remaining need ----------------
__device__ __forceinline__ void scan_boundary(unsigned* hist, unsigned* gsum, int NG,
                                              int tid, int* sh_sel, int* sh_need,
                                              int* sh_take, unsigned* sh_gat) {
    if (tid < NG) {
        unsigned t = 0;
        int base = tid * 32;
#pragma unroll 8
        for (int i = 0; i < 32; i++) t += hist[base + i];
        gsum[tid] = t;
    }
    __syncthreads();
    if (tid == 0) {
        int need = *sh_need;
        unsigned acc = 0;
        int g = NG - 1;
        for (; g >= 0; g--) {
            if (acc + gsum[g] >= (unsigned)need) break;
            acc += gsum[g];
        }
        if (g < 0) {
            *sh_take = 1;  // fewer than `need` candidates total
        } else {
            int bin = g * 32 + 31;
            for (;; bin--) {
                if (acc + hist[bin] >= (unsigned)need) break;
                acc += hist[bin];
            }
            *sh_sel = bin;
            *sh_need = need - (int)acc;          // remaining need inside boundary bin
            *sh_gat = acc + hist[bin];           // total items with key >= bin prefix
        }
    }
    __syncthreads();
}

// ---------------- K2: per-(b,c) exact top-1000, SINGLE g_scores pass + decode ----------------
__global__ __launch_bounds__(1024) void select_kernel(const float4* __restrict__ anchors,
                                                      const float4* __restrict__ deltas) {
    int bc = blockIdx.x;
    int tid = threadIdx.x;
    const float* sc = g_scores + (size_t)bc * NN;
    const float4* sc4 = (const float4*)sc;

    __shared__ __align__(16) unsigned char sraw[HBPAD * 4];   // 36 KB overlay
    unsigned* hist = (unsigned*)sraw;                         // sample + fallback hists
    unsigned long long* arr = (unsigned long long*)sraw;      // 32 KB gather/sort buffer
    __shared__ unsigned gsum[288];
    __shared__ int sh_sel, sh_need, sh_take, sh_cnt;
    __shared__ unsigned sh_gat, sh_T;

    // ---- phase 0: histogram 4096 sampled keys, select 48th-largest bin floor as T ----
    for (int i = tid; i < HBPAD; i += 1024) hist[i] = 0;
    if (tid == 0) { sh_need = 48; sh_take = 0; }
    __syncthreads();
    for (int i = tid; i < 4096; i += 1024) {
        float s = sc[i * 47];                  // 47*4095 = 192465 < NN
        if (s > SCORE_T) {
            int bin = (int)(__float_as_uint(s) >> 12) - (int)P_LO;
            bin = min(max(bin, 0), HB - 1);
            atomicAdd(&hist[bin], 1u);
        }
    }
    __syncthreads();
    scan_boundary(hist, gsum, 282, tid, &sh_sel, &sh_need, &sh_take, &sh_gat);
    if (tid == 0) {
        unsigned t = sh_take ? KT_MIN : ((P_LO + (unsigned)sh_sel) << 12);
        sh_T = (t >= KT_MIN) ? t : KT_MIN;
    }
    __syncthreads();
    unsigned T = sh_T;
    __syncthreads();

    // ---- phase 1: single-pass gather of keys >= T into 4096-slot buffer ----
    for (int i = tid; i < 4096; i += 1024) arr[i] = 0ull;
    if (tid == 0) sh_cnt = 0;
    __syncthreads();
    for (int n4 = tid; n4 < NN / 4; n4 += 1024) {
        float4 v = sc4[n4];
        float sv[4] = {v.x, v.y, v.z, v.w};
#pragma unroll
        for (int c = 0; c < 4; c++) {
            float s = sv[c];
            if (s > SCORE_T) {
                unsigned k = __float_as_uint(s);
                if (k >= T) {
                    int p = atomicAdd(&sh_cnt, 1);
                    unsigned n = (unsigned)(n4 * 4 + c);
                    if (p < 4096)
                        arr[p] = ((unsigned long long)k << 32) |
                                 (unsigned long long)(0xFFFFFFFFu - n);
                }
            }
        }
    }
    __syncthreads();
    int cnt = sh_cnt;
    bool fast = (cnt <= 4096) && (cnt >= KK || T == KT_MIN);

    if (!fast) {
        // ---- exact fallback (cold): full two-pass radix-select over g_scores ----
        __syncthreads();
        for (int i = tid; i < HBPAD; i += 1024) hist[i] = 0;
        if (tid == 0) { sh_need = KK; sh_take = 0; }
        __syncthreads();
        for (int n4 = tid; n4 < NN / 4; n4 += 1024) {
            float4 v = sc4[n4];
            float sv[4] = {v.x, v.y, v.z, v.w};
#pragma unroll
            for (int c = 0; c < 4; c++) {
                float s = sv[c];
                if (s > SCORE_T) {
                    int bin = (int)(__float_as_uint(s) >> 12) - (int)P_LO;
                    bin = min(max(bin, 0), HB - 1);
                    atomicAdd(&hist[bin], 1u);
                }
            }
        }
        __syncthreads();
        scan_boundary(hist, gsum, 282, tid, &sh_sel, &sh_need, &sh_take, &sh_gat);
        unsigned Kt;
        if (sh_take) {
            Kt = KT_MIN;
        } else {
            unsigned prefix = P_LO + (unsigned)sh_sel;
            Kt = prefix << 12;
            if (sh_gat > 4096u) {
                __syncthreads();
                for (int i = tid; i < 4096; i += 1024) hist[i] = 0;
                __syncthreads();
                for (int n4 = tid; n4 < NN / 4; n4 += 1024) {
                    float4 v = sc4[n4];
                    float sv[4] = {v.x, v.y, v.z, v.w};
#pragma unroll
                    for (int c = 0; c < 4; c++) {
                        float s = sv[c];
                        if (s > SCORE_T) {
                            unsigned k = __float_as_uint(s);
                            if ((k >> 12) == prefix) atomicAdd(&hist[k & 0xFFF], 1u);
                        }
                    }
                }
                __syncthreads();
                scan_boundary(hist, gsum, 128, tid, &sh_sel, &sh_need, &sh_take, &sh_gat);
                Kt = (prefix << 12) | (unsigned)sh_sel;
            }
        }
        __syncthreads();
        for (int i = tid; i < 4096; i += 1024) arr[i] = 0ull;
        if (tid == 0) sh_cnt = 0;
        __syncthreads();
        for (int n4 = tid; n4 < NN / 4; n4 += 1024) {
            float4 v = sc4[n4];
            float sv[4] = {v.x, v.y, v.z, v.w};
#pragma unroll
            for (int c = 0; c < 4; c++) {
                float s = sv[c];
                if (s > SCORE_T) {
                    unsigned k = __float_as_uint(s);
                    if (k >= Kt) {
                        int p = atomicAdd(&sh_cnt, 1);
                        unsigned n = (unsigned)(n4 * 4 + c);
                        if (p < 4096)
                            arr[p] = ((unsigned long long)k << 32) |
                                     (unsigned long long)(0xFFFFFFFFu - n);
                    }
                }
            }
        }
        __syncthreads();
    }

    // ---- phase 2: bitonic sort 4096 desc (score desc, idx asc on ties) ----
    for (int k = 2; k <= 4096; k <<= 1)
        for (int j = k >> 1; j > 0; j >>= 1) {
            __syncthreads();
            for (int i = tid; i < 4096; i += 1024) {
                int ixj = i ^ j;
                if (ixj > i) {
                    unsigned long long a = arr[i], b = arr[ixj];
                    if (((i & k) == 0) ? (a < b) : (a > b)) { arr[i] = b; arr[ixj] = a; }
                }
            }
        }
    __syncthreads();

    // ---- epilogue: write topval + decode box inline ----
    if (tid < KK) {
        unsigned long long v = arr[tid];
        float val;
        int idx;
        if (v) {
            val = __uint_as_float((unsigned)(v >> 32));
            idx = (int)(0xFFFFFFFFu - (unsigned)v);
        } else {
            val = -1.0f;    // padding; cannot surface in output
            idx = tid;
        }
        g_topval[bc * KK + tid] = val;
        int b = bc / CC;
        float4 an = anchors[idx];
        float4 dl = deltas[(size_t)b * NN + idx];
        float acx = (an.x + an.z) * 0.5f, acy = (an.y + an.w) * 0.5f;
        float aw = fmaxf(an.z - an.x, 1.0f), ah = fmaxf(an.w - an.y, 1.0f);
        float cx = dl.x * aw + acx, cy = dl.y * ah + acy;
        float w = expf(fminf(dl.z, 4.0f)) * aw;
        float h = expf(fminf(dl.w, 4.0f)) * ah;
        g_topbox[bc * KK + tid] = make_float4(cx - w * 0.5f, cy - h * 0.5f,
                                              cx + w * 0.5f, cy + h * 0.5f);
    }
}

// ---------------- K3: FUSED NMS (mask chunks in smem + overlapped greedy solve) ----------------
__device__ __forceinline__ bool iou_sup(float4 bi, float ai, float4 bj, float aj, bool after) {
    float x1 = fmaxf(bi.x, bj.x), y1 = fmaxf(bi.y, bj.y);
    float x2 = fminf(bi.z, bj.z), y2 = fminf(bi.w, bj.w);
    float inter = fmaxf(x2 - x1, 0.0f) * fmaxf(y2 - y1, 0.0f);
    return after && (inter > 0.5f * fmaxf(ai + aj - inter, 1e-6f));
}

__global__ __launch_bounds__(1024) void nms_fused_kernel() {
    int bc = blockIdx.x;
    int tid = threadIdx.x;
    int lane = tid & 31;
    int wid = tid >> 5;

    __shared__ float4 sb[1024];          // padded: rows 1000..1023 are zero boxes
    __shared__ float sa[1024];
    __shared__ unsigned M[2][32][32];    // double-buffered mask chunk [buf][row][word]
    __shared__ unsigned keepw[32];

    {
        int i = tid;
        float4 bx = (i < KK) ? g_topbox[bc * KK + i] : make_float4(0.f, 0.f, 0.f, 0.f);
        sb[i] = bx;
        sa[i] = (bx.z - bx.x) * (bx.w - bx.y);
    }
    __syncthreads();

    // compute mask chunk cc into M[buf]: units flattened as u = (w-cc)*32 + row
    // unit (row, w): 32 lanes IoU row (cc*32+row) vs cols w*32+lane -> ballot.
    auto compute_chunk = [&](int cc, int buf, int k, int nwrp) {
        int wpc = 32 - cc;                 // words per row
        int total = wpc * 32;
        int base = cc * 32;
        for (int u = k; u < total; u += nwrp) {
            int row = u & 31;
            int w = cc + (u >> 5);
            int i = base + row;
            int j = (w << 5) + lane;
            float4 bi = sb[i];
            float ai = sa[i];
            bool sup = iou_sup(bi, ai, sb[j], sa[j], j > i);
            unsigned bits = __ballot_sync(0xFFFFFFFFu, sup);
            if (lane == 0) M[buf][row][w] = bits;
        }
    };

    // pre-compute chunk 0 with all 32 warps
    compute_chunk(0, 0, wid, 32);
    __syncthreads();

    unsigned removed = 0u;               // warp 0: lane l owns columns l*32..l*32+31
    for (int c = 0; c < 32; c++) {
        if (wid > 0) {
            if (c < 31) compute_chunk(c + 1, (c + 1) & 1, wid - 1, 31);
        } else {
            // greedy triangle solve of chunk c (lane c's column words are the diagonal)
            const unsigned (*Mc)[32] = M[c & 1];
            unsigned w[32];
#pragma unroll
            for (int s = 0; s < 32; s++) w[s] = Mc[s][lane];
            unsigned kb = ~removed;
            if (c == 31) kb &= 0xFFu;      // rows 1000..1023 are padding
#pragma unroll
            for (int s = 0; s < 32; s++) {
                unsigned m = (unsigned)(-(int)((kb >> s) & 1u));
                kb &= ~(w[s] & m);
            }
            kb = __shfl_sync(0xFFFFFFFFu, kb, c);
            unsigned a0 = 0, a1 = 0, a2 = 0, a3 = 0;
#pragma unroll
            for (int s = 0; s < 32; s += 4) {
                a0 |= w[s + 0] & (unsigned)(-(int)((kb >> (s + 0)) & 1u));
                a1 |= w[s + 1] & (unsigned)(-(int)((kb >> (s + 1)) & 1u));
                a2 |= w[s + 2] & (unsigned)(-(int)((kb >> (s + 2)) & 1u));
                a3 |= w[s + 3] & (unsigned)(-(int)((kb >> (s + 3)) & 1u));
            }
            removed |= (a0 | a1) | (a2 | a3);
            if (lane == 0) keepw[c] = kb;
        }
        __syncthreads();
    }

    // ---- epilogue (warp 0): score threshold, g_val, compact survivors ----
    if (wid == 0) {
        int cnt = 0;
        for (int w = 0; w < 32; w++) {
            unsigned kb = keepw[w];
            int i = w * 32 + lane;
            float v = (i < KK) ? g_topval[bc * KK + i] : -1.0f;
            bool valid = (i < KK) && ((kb >> lane) & 1u) && (v > SCORE_T);
            if (i < KK) g_val[bc * KK + i] = valid ? v : 0.0f;
            unsigned bal = __ballot_sync(0xFFFFFFFFu, valid);
            int pos = cnt + __popc(bal & ((1u << lane) - 1u));
            if (valid) {
                g_cval[bc * KK + pos] = v;      // survivors stay score-descending
                g_cidx[bc * KK + pos] = i;
            }
            cnt += __popc(bal);
        }
        if (lane == 0) g_cnt[bc] = cnt;
    }
}

// ---------------- K4: per-image top-100 over 9 classes ----------------
__global__ __launch_bounds__(512) void final_kernel(float* __restrict__ out) {
    int b = blockIdx.x;
    int tid = threadIdx.x;
    __shared__ unsigned long long arr[1024];
    for (int i = tid; i < 1024; i += 512) arr[i] = 0ull;
    __syncthreads();
    // only the top-100 of each class can reach the global top-100
    for (int s = tid; s < 900; s += 512) {
        int c = s / 100, r = s % 100;
        int bc = b * 9 + c;
        if (r < g_cnt[bc]) {
            float v = g_cval[bc * KK + r];
            int k = g_cidx[bc * KK + r];
            unsigned flat = (unsigned)(c * KK + k);
            arr[s] = ((unsigned long long)__float_as_uint(v) << 32) |
                     (unsigned long long)(0xFFFFFFFFu - flat);
        }
    }
    __syncthreads();
    for (int k = 2; k <= 1024; k <<= 1)
        for (int j = k >> 1; j > 0; j >>= 1) {
            __syncthreads();
            for (int i = tid; i < 1024; i += 512) {
                int ixj = i ^ j;
                if (ixj > i) {
                    unsigned long long a = arr[i], bv = arr[ixj];
                    if (((i & k) == 0) ? (a < bv) : (a > bv)) { arr[i] = bv; arr[ixj] = a; }
                }
            }
        }
    __syncthreads();

    float* o = out + (size_t)b * MAXDET * 6;
    if (tid < MAXDET) {
        unsigned long long v = arr[tid];
        if (v) {
            unsigned flat = 0xFFFFFFFFu - (unsigned)v;
            int c = flat / KK, k2 = flat % KK;
            float4 bx = g_topbox[(b * 9 + c) * KK + k2];
            float scv = __uint_as_float((unsigned)(v >> 32));
            o[tid * 6 + 0] = bx.x; o[tid * 6 + 1] = bx.y;
            o[tid * 6 + 2] = bx.z; o[tid * 6 + 3] = bx.w;
            o[tid * 6 + 4] = scv;  o[tid * 6 + 5] = (float)c;
        }
    }
    __syncthreads();
    // exact-tie fallback: < 100 positive detections -> zero-score entries by ascending flat idx
    if (tid == 0 && arr[MAXDET - 1] == 0ull) {
        int f = 0;
        for (int t = 0; t < MAXDET; t++) {
            if (arr[t]) continue;
            while (f < 9000 && g_val[(size_t)b * 9000 + f] != 0.0f) f++;
            int c = 0, k2 = 0;
            float4 bx = make_float4(0.f, 0.f, 0.f, 0.f);
            if (f < 9000) {
                c = f / KK; k2 = f % KK;
                bx = g_topbox[(b * 9 + c) * KK + k2];
                f++;
            }
            o[t * 6 + 0] = bx.x; o[t * 6 + 1] = bx.y;
            o[t * 6 + 2] = bx.z; o[t * 6 + 3] = bx.w;
            o[t * 6 + 4] = 0.0f; o[t * 6 + 5] = (float)c;
        }
    }
}

// ---------------- launch ----------------
extern "C" void kernel_launch(void* const* d_in, const int* in_sizes, int n_in,
                              void* d_out, int out_size) {
    (void)in_sizes; (void)n_in; (void)out_size;
    const float* anchors = (const float*)d_in[0];
    const float* deltas  = (const float*)d_in[1];
    const float* cls     = (const float*)d_in[2];
    const float* obj     = (const float*)d_in[3];
    float* out = (float*)d_out;

    score_kernel<<<dim3(NN / 256, BB), 256>>>(cls, obj);
    select_kernel<<<BC, 1024>>>((const float4*)anchors, (const float4*)deltas);
    nms_fused_kernel<<<BC, 1024>>>();
    final_kernel<<<BB, 512>>>(out);
}